// round 15
// baseline (speedup 1.0000x reference)
#include <cuda_runtime.h>
#include <math.h>

#define BB 64
#define QQ 900
#define GG 100
#define NC 10
#define NC1 11
#define NF4 225    // 900/4 float4 per row
#define KCHUNK 25  // gt rows per cost-kernel z-block

// -------- device scratch (static: no allocation) --------
__device__ float  g_costT[BB * GG * QQ];   // transposed cost: [b][k][q]
__device__ float  g_logZ[BB * QQ];         // log-partition per (b,q)
__device__ unsigned long long g_rowpack[BB * GG];  // packed (fkey(min), argmin q)
__device__ int    g_vlist[BB * GG];
__device__ int    g_nvalid[BB];
__device__ int    g_done;
__device__ int    g_nmatched;
__device__ double g_cls_num;
__device__ double g_cls_den;
__device__ double g_l1;
__device__ double g_gl;

// ordered-uint key: monotone bijection float -> uint32 (handles negatives)
__device__ __forceinline__ unsigned int fkey(float f) {
    unsigned int b = __float_as_uint(f);
    return (b & 0x80000000u) ? ~b : (b | 0x80000000u);
}
__device__ __forceinline__ float fkey_inv(unsigned int key) {
    unsigned int b = (key & 0x80000000u) ? (key ^ 0x80000000u) : ~key;
    return __uint_as_float(b);
}

// one block per batch: compact valid gt indices, init rowpack (+ globals)
__global__ void prep_kernel(const int* __restrict__ gt_classes) {
    int b = blockIdx.x;
    for (int k = threadIdx.x; k < GG; k += blockDim.x)
        g_rowpack[b * GG + k] = 0xFFFFFFFFFFFFFFFFull;
    if (threadIdx.x == 0) {
        if (b == 0) {
            g_done = 0;
            g_nmatched = 0;
            g_cls_num = 0.0;
            g_cls_den = 0.0;
            g_l1 = 0.0;
            g_gl = 0.0;
        }
        int n = 0;
        for (int g = 0; g < GG; g++) {
            if (gt_classes[b * GG + g] >= 0) g_vlist[b * GG + n++] = g;
        }
        g_nvalid[b] = n;
    }
}

// cost[b][q][k] -> g_costT[(b*GG + k)*QQ + q]; k split across gridDim.z
// chunks of KCHUNK; logZ written by z==0 only. Per-row (min, argmin) fused
// via redux + packed atomicMin (bit-identical: min value, tie -> smallest q).
__global__ void cost_kernel(const float* __restrict__ logits,
                            const float* __restrict__ pboxes,
                            const int*   __restrict__ gtc,
                            const float* __restrict__ gboxes) {
    int b = blockIdx.y;
    int q = blockIdx.x * blockDim.x + threadIdx.x;
    int kc0 = blockIdx.z * KCHUNK;
    const bool valid = q < QQ;
    const int qc = valid ? q : QQ - 1;
    const int lane = threadIdx.x & 31;

    __shared__ float sgx0[KCHUNK], sgy0[KCHUNK], sgx1[KCHUNK], sgy1[KCHUNK], sga[KCHUNK];
    __shared__ float sgcx[KCHUNK], sgcy[KCHUNK], sgw[KCHUNK], sgh[KCHUNK];
    __shared__ int   scls[KCHUNK];
    __shared__ int   sn;

    if (threadIdx.x == 0) sn = g_nvalid[b];
    __syncthreads();
    int n = sn;
    int kc1 = min(n, kc0 + KCHUNK);
    if (kc0 >= kc1) return;   // block-uniform

    for (int k = kc0 + threadIdx.x; k < kc1; k += blockDim.x) {
        int kk = k - kc0;
        int gi = g_vlist[b * GG + k];
        const float* gb = gboxes + ((size_t)(b * GG + gi)) * 4;
        float cx = gb[0], cy = gb[1], w = gb[2], h = gb[3];
        float x0 = cx - w * 0.5f, y0 = cy - h * 0.5f;
        float x1 = cx + w * 0.5f, y1 = cy + h * 0.5f;
        sgx0[kk] = x0; sgy0[kk] = y0; sgx1[kk] = x1; sgy1[kk] = y1;
        sga[kk] = fmaxf(x1 - x0, 0.f) * fmaxf(y1 - y0, 0.f);
        sgcx[kk] = cx; sgcy[kk] = cy; sgw[kk] = w; sgh[kk] = h;
        int c = gtc[b * GG + gi];
        scls[kk] = (c < 0) ? 0 : (c > NC - 1 ? NC - 1 : c);
    }
    __syncthreads();

    // softmax over NC1 logits
    const float* lg = logits + ((size_t)(b * QQ + qc)) * NC1;
    float e[NC1];
    float mx = lg[0];
#pragma unroll
    for (int c = 1; c < NC1; c++) mx = fmaxf(mx, lg[c]);
    float s = 0.f;
#pragma unroll
    for (int c = 0; c < NC1; c++) { e[c] = expf(lg[c] - mx); s += e[c]; }
    float inv_s = 1.0f / s;
    if (blockIdx.z == 0 && valid) g_logZ[b * QQ + q] = mx + logf(s);

    const float* pb = pboxes + ((size_t)(b * QQ + qc)) * 4;
    float pcx = pb[0], pcy = pb[1], pw = pb[2], ph = pb[3];
    float px0 = pcx - pw * 0.5f, py0 = pcy - ph * 0.5f;
    float px1 = pcx + pw * 0.5f, py1 = pcy + ph * 0.5f;
    float pa = fmaxf(px1 - px0, 0.f) * fmaxf(py1 - py0, 0.f);

    float* outc = g_costT + (size_t)b * GG * QQ + q;
    for (int k = kc0; k < kc1; k++) {
        int kk = k - kc0;
        float clsc = -(e[scls[kk]] * inv_s);
        float l1 = fabsf(pcx - sgcx[kk]) + fabsf(pcy - sgcy[kk]) +
                   fabsf(pw - sgw[kk]) + fabsf(ph - sgh[kk]);
        float gx0 = sgx0[kk], gy0 = sgy0[kk], gx1 = sgx1[kk], gy1 = sgy1[kk];
        float ltx = fmaxf(px0, gx0), lty = fmaxf(py0, gy0);
        float rbx = fminf(px1, gx1), rby = fminf(py1, gy1);
        float iw = fmaxf(rbx - ltx, 0.f), ih = fmaxf(rby - lty, 0.f);
        float inter = iw * ih;
        float uni = pa + sga[kk] - inter;
        float iou = inter / fmaxf(uni, 1e-6f);
        float ex0 = fminf(px0, gx0), ey0 = fminf(py0, gy0);
        float ex1 = fmaxf(px1, gx1), ey1 = fmaxf(py1, gy1);
        float ew = fmaxf(ex1 - ex0, 0.f), eh = fmaxf(ey1 - ey0, 0.f);
        float enc = ew * eh;
        float giou = iou - (enc - uni) / fmaxf(enc, 1e-6f);
        float cval = 2.0f * clsc + 5.0f * l1 - 2.0f * giou;
        if (valid) outc[(size_t)k * QQ] = cval;

        // fused row (min, argmin): 2 hardware reduces + 1 packed atomic/warp
        unsigned int key = valid ? fkey(cval) : 0xFFFFFFFFu;
        unsigned int mkey = __reduce_min_sync(0xffffffffu, key);
        unsigned int qsel = (key == mkey) ? (unsigned int)q : 0xFFFFFFFFu;
        unsigned int qmin = __reduce_min_sync(0xffffffffu, qsel);
        if (lane == 0 && mkey != 0xFFFFFFFFu)
            atomicMin(&g_rowpack[b * GG + k],
                      ((unsigned long long)mkey << 32) | qmin);
    }
}

// Warm-started Jonker-Volgenant (fp32, v=0 start — verified exact R4-R14)
// with the LOSS FUSED into the tail: each block computes its batch's loss
// terms from sp[] in shared memory; last block finalizes the scalar.
__global__ void __launch_bounds__(64) jv_kernel(
        const float* __restrict__ logits,
        const float* __restrict__ pboxes,
        const int*   __restrict__ gtc,
        const float* __restrict__ gboxes,
        float* __restrict__ out) {
    const int b = blockIdx.x;
    const int tid = threadIdx.x;
    const int wid = tid >> 5;
    const int lane = tid & 31;
    const int n = g_nvalid[b];
    const float FNAN = __int_as_float(0x7fc00000);

    __shared__ __align__(16) float sv[QQ + 4];     // v duals
    __shared__ __align__(16) float sminv[QQ + 4];  // path minima (NaN = used)
    __shared__ float su[GG];                       // u duals
    __shared__ int   sway[QQ + 4];
    __shared__ int   sp[QQ + 4];                   // assigned row per col, -1 free
    __shared__ int   susedList[GG + 2];
    __shared__ float sDused[GG + 2];
    __shared__ int   sfree[GG + 1];
    __shared__ unsigned long long srowpk[GG];
    __shared__ unsigned long long swcomb[2][2];    // [parity][warp]
    __shared__ double sred[4][2];
    __shared__ int   snfree;

    for (int q = tid; q < QQ + 4; q += 64) { sv[q] = 0.0f; sp[q] = -1; }
    for (int i = tid; i < n; i += 64) srowpk[i] = g_rowpack[b * GG + i];
    __syncthreads();

    // greedy assignment from row minima (decisions serial, data from LDS)
    if (tid == 0) {
        int nf = 0;
        for (int i = 0; i < n; i++) {
            unsigned long long pk = srowpk[i];
            su[i] = fkey_inv((unsigned int)(pk >> 32));
            int jm = (int)(pk & 0xFFFFFFFFull);
            if (sp[jm] < 0) sp[jm] = i;
            else sfree[nf++] = i;
        }
        snfree = nf;
    }
    __syncthreads();
    const int nfree = snfree;

    const float* Cbase = g_costT + (size_t)b * GG * QQ;

    for (int fi = 0; fi < nfree; fi++) {
        const int f = sfree[fi];
        // reset minv (vectorized, owner-exclusive)
#pragma unroll
        for (int s = 0; s < 4; s++) {
            int f4 = tid + (s << 6);
            if (f4 < NF4)
                *(float4*)&sminv[f4 << 2] = make_float4(1e30f, 1e30f, 1e30f, 1e30f);
        }
        __syncthreads();

        int i0 = f;
        int j0 = -1;       // root
        float D = 0.0f;
        int cnt = 0;
        int par = 0;

        while (true) {
            const float ueff = su[i0] - D;
            if (tid == 0) { susedList[cnt] = j0; sDused[cnt] = D; }
            if (j0 >= 0 && (((j0 >> 2) & 63) == tid)) sminv[j0] = FNAN; // owner marks used
            cnt++;

            const float4* __restrict__ Crow4 =
                (const float4*)(Cbase + (size_t)i0 * QQ);

            // batched vector loads: full MLP, one L2 round trip
            float4 c4[4];
#pragma unroll
            for (int s = 0; s < 4; s++) {
                int f4 = tid + (s << 6);
                c4[s] = (f4 < NF4) ? __ldg(&Crow4[f4])
                                   : make_float4(1e30f, 1e30f, 1e30f, 1e30f);
            }

            float lmin = 1e30f;
            int lq = QQ;
#pragma unroll
            for (int s = 0; s < 4; s++) {
                int f4 = tid + (s << 6);
                if (f4 < NF4) {
                    int q0 = f4 << 2;
                    float4 v4 = *(const float4*)&sv[q0];
                    float4 m4 = *(const float4*)&sminv[q0];
                    float cur;
                    cur = c4[s].x - ueff - v4.x;
                    if (cur < m4.x) { m4.x = cur; sway[q0] = j0; }       // false if NaN
                    cur = c4[s].y - ueff - v4.y;
                    if (cur < m4.y) { m4.y = cur; sway[q0 + 1] = j0; }
                    cur = c4[s].z - ueff - v4.z;
                    if (cur < m4.z) { m4.z = cur; sway[q0 + 2] = j0; }
                    cur = c4[s].w - ueff - v4.w;
                    if (cur < m4.w) { m4.w = cur; sway[q0 + 3] = j0; }
                    *(float4*)&sminv[q0] = m4;
                    if (m4.x < lmin) { lmin = m4.x; lq = q0; }           // NaN excluded
                    if (m4.y < lmin) { lmin = m4.y; lq = q0 + 1; }
                    if (m4.z < lmin) { lmin = m4.z; lq = q0 + 2; }
                    if (m4.w < lmin) { lmin = m4.w; lq = q0 + 3; }
                }
            }
            // per-warp argmin via hardware reduces, then cross-warp packed min.
            // Double-buffered on phase parity: one barrier per phase.
            unsigned int key = fkey(lmin);
            unsigned int mkey = __reduce_min_sync(0xffffffffu, key);
            unsigned int qsel = (key == mkey) ? (unsigned int)lq : 0xffffffffu;
            unsigned int qmin = __reduce_min_sync(0xffffffffu, qsel);
            if (lane == 0)
                swcomb[par][wid] = ((unsigned long long)mkey << 32) | qmin;
            __syncthreads();
            unsigned long long comb = min(swcomb[par][0], swcomb[par][1]);
            par ^= 1;
            D = fkey_inv((unsigned int)(comb >> 32));  // bit-identical to winner
            j0 = (int)(comb & 0xFFFFFFFFull);
            int pj = sp[j0];
            if (pj < 0) break;
            i0 = pj;
        }

        // commit duals over used columns (distinct rows & cols -> race-free)
        for (int t = tid; t < cnt; t += 64) {
            int j = susedList[t];
            float dd = D - sDused[t];
            if (j < 0) su[f] += dd;
            else { su[sp[j]] += dd; sv[j] -= dd; }
        }
        __syncthreads();
        if (tid == 0) {
            int jj = j0;
            while (jj >= 0) {
                int jn = sway[jj];
                sp[jj] = (jn < 0) ? f : sp[jn];
                jj = jn;
            }
        }
        __syncthreads();
    }

    // ---- fused loss over this batch's 900 queries ----
    double nllw = 0.0, wsum = 0.0, l1acc = 0.0, glacc = 0.0;
    for (int q = tid; q < QQ; q += 64) {
        int r = sp[q];
        int mg = (r >= 0) ? g_vlist[b * GG + r] : -1;
        int idx = b * QQ + q;
        int t = (mg >= 0) ? __ldg(&gtc[b * GG + mg]) : NC;
        float logp = __ldg(&logits[(size_t)idx * NC1 + t]) - g_logZ[idx];
        float wt = (t == NC) ? 0.1f : 1.0f;
        nllw += (double)(wt * (-logp));
        wsum += (double)wt;

        if (mg >= 0) {
            const float* pb = pboxes + (size_t)idx * 4;
            const float* gb = gboxes + ((size_t)(b * GG + mg)) * 4;
            float pcx = pb[0], pcy = pb[1], pw = pb[2], ph = pb[3];
            float gcx = gb[0], gcy = gb[1], gw = gb[2], gh = gb[3];
            l1acc += (double)(fabsf(pcx - gcx) + fabsf(pcy - gcy) +
                              fabsf(pw - gw) + fabsf(ph - gh));
            float px0 = pcx - pw * 0.5f, py0 = pcy - ph * 0.5f;
            float px1 = pcx + pw * 0.5f, py1 = pcy + ph * 0.5f;
            float gx0 = gcx - gw * 0.5f, gy0 = gcy - gh * 0.5f;
            float gx1 = gcx + gw * 0.5f, gy1 = gcy + gh * 0.5f;
            float pa = fmaxf(px1 - px0, 0.f) * fmaxf(py1 - py0, 0.f);
            float ga = fmaxf(gx1 - gx0, 0.f) * fmaxf(gy1 - gy0, 0.f);
            float ltx = fmaxf(px0, gx0), lty = fmaxf(py0, gy0);
            float rbx = fminf(px1, gx1), rby = fminf(py1, gy1);
            float iw = fmaxf(rbx - ltx, 0.f), ih = fmaxf(rby - lty, 0.f);
            float inter = iw * ih;
            float uni = pa + ga - inter;
            float iou = inter / fmaxf(uni, 1e-6f);
            float ex0 = fminf(px0, gx0), ey0 = fminf(py0, gy0);
            float ex1 = fmaxf(px1, gx1), ey1 = fmaxf(py1, gy1);
            float ew = fmaxf(ex1 - ex0, 0.f), eh = fmaxf(ey1 - ey0, 0.f);
            float enc = ew * eh;
            float giou = iou - (enc - uni) / fmaxf(enc, 1e-6f);
            glacc += (double)(1.0f - giou);
        }
    }

    // block reduce (2 warps): shuffle within warp, combine via smem
#pragma unroll
    for (int off = 16; off; off >>= 1) {
        nllw  += __shfl_down_sync(0xffffffffu, nllw, off);
        wsum  += __shfl_down_sync(0xffffffffu, wsum, off);
        l1acc += __shfl_down_sync(0xffffffffu, l1acc, off);
        glacc += __shfl_down_sync(0xffffffffu, glacc, off);
    }
    if (lane == 0) {
        sred[0][wid] = nllw; sred[1][wid] = wsum;
        sred[2][wid] = l1acc; sred[3][wid] = glacc;
    }
    __syncthreads();
    if (tid == 0) {
        atomicAdd(&g_cls_num, sred[0][0] + sred[0][1]);
        atomicAdd(&g_cls_den, sred[1][0] + sred[1][1]);
        atomicAdd(&g_l1,      sred[2][0] + sred[2][1]);
        atomicAdd(&g_gl,      sred[3][0] + sred[3][1]);
        atomicAdd(&g_nmatched, n);
        __threadfence();
        int done = atomicAdd(&g_done, 1);
        if (done == BB - 1) {   // last block finalizes the scalar
            int nm = g_nmatched;
            if (nm < 1) nm = 1;
            double nmd = (double)nm;
            double cls = g_cls_num / g_cls_den;
            out[0] = (float)(2.0 * cls + 5.0 * g_l1 / nmd + 2.0 * g_gl / nmd);
        }
    }
}

extern "C" void kernel_launch(void* const* d_in, const int* in_sizes, int n_in,
                              void* d_out, int out_size) {
    const float* pred_logits = (const float*)d_in[0];
    const float* pred_boxes  = (const float*)d_in[1];
    const int*   gt_classes  = (const int*)d_in[2];
    const float* gt_boxes    = (const float*)d_in[3];
    float* out = (float*)d_out;

    prep_kernel<<<BB, 128>>>(gt_classes);

    dim3 cgrid((QQ + 127) / 128, BB, (GG + KCHUNK - 1) / KCHUNK);
    cost_kernel<<<cgrid, 128>>>(pred_logits, pred_boxes, gt_classes, gt_boxes);

    jv_kernel<<<BB, 64>>>(pred_logits, pred_boxes, gt_classes, gt_boxes, out);
}

// round 16
// speedup vs baseline: 1.1269x; 1.1269x over previous
#include <cuda_runtime.h>
#include <math.h>

#define BB 64
#define QQ 900
#define GG 100
#define NC 10
#define NC1 11
#define NF4 225    // 900/4 float4 per row
#define KCHUNK 25  // gt rows per cost-kernel z-block

// -------- device scratch (static: no allocation) --------
__device__ float  g_costT[BB * GG * QQ];   // transposed cost: [b][k][q]
__device__ float  g_logZ[BB * QQ];         // log-partition per (b,q), reused by loss
__device__ unsigned long long g_rowpack[BB * GG];  // packed (fkey(min), argmin q)
__device__ int    g_vlist[BB * GG];
__device__ int    g_nvalid[BB];
__device__ int    g_match[BB * QQ];
__device__ int    g_nmatched;
__device__ int    g_loss_done;
__device__ double g_cls_num;
__device__ double g_cls_den;
__device__ double g_l1;
__device__ double g_gl;

// ordered-uint key: monotone bijection float -> uint32 (handles negatives)
__device__ __forceinline__ unsigned int fkey(float f) {
    unsigned int b = __float_as_uint(f);
    return (b & 0x80000000u) ? ~b : (b | 0x80000000u);
}
__device__ __forceinline__ float fkey_inv(unsigned int key) {
    unsigned int b = (key & 0x80000000u) ? (key ^ 0x80000000u) : ~key;
    return __uint_as_float(b);
}

// one block (128 threads) per batch: order-preserving ballot compaction of
// valid gt indices; rowpack init; globals init on block 0.
__global__ void __launch_bounds__(128) prep_kernel(const int* __restrict__ gt_classes) {
    const int b = blockIdx.x;
    const int tid = threadIdx.x;
    const int lane = tid & 31;
    const int wid = tid >> 5;

    for (int k = tid; k < GG; k += 128)
        g_rowpack[b * GG + k] = 0xFFFFFFFFFFFFFFFFull;
    if (b == 0 && tid == 0) {
        g_nmatched = 0;
        g_loss_done = 0;
        g_cls_num = 0.0;
        g_cls_den = 0.0;
        g_l1 = 0.0;
        g_gl = 0.0;
    }

    bool valid = (tid < GG) && (gt_classes[b * GG + tid] >= 0);
    unsigned int ball = __ballot_sync(0xffffffffu, valid);
    int lanepre = __popc(ball & ((1u << lane) - 1u));
    int wcount = __popc(ball);

    __shared__ int woff[4];
    if (lane == 0) woff[wid] = wcount;
    __syncthreads();
    int base = 0;
#pragma unroll
    for (int w = 0; w < 4; w++) {
        if (w < wid) base += woff[w];
    }
    if (valid) g_vlist[b * GG + base + lanepre] = tid;
    if (tid == 96) {   // last warp's leader computes total
        int n = woff[0] + woff[1] + woff[2] + woff[3];
        g_nvalid[b] = n;
    }
}

// cost[b][q][k] -> g_costT[(b*GG + k)*QQ + q]; k split across gridDim.z
// chunks of KCHUNK; logZ written by z==0 only. Per-row (min, argmin) fused
// via redux + packed atomicMin (bit-identical: min value, tie -> smallest q).
__global__ void cost_kernel(const float* __restrict__ logits,
                            const float* __restrict__ pboxes,
                            const int*   __restrict__ gtc,
                            const float* __restrict__ gboxes) {
    int b = blockIdx.y;
    int q = blockIdx.x * blockDim.x + threadIdx.x;
    int kc0 = blockIdx.z * KCHUNK;
    const bool valid = q < QQ;
    const int qc = valid ? q : QQ - 1;
    const int lane = threadIdx.x & 31;

    __shared__ float sgx0[KCHUNK], sgy0[KCHUNK], sgx1[KCHUNK], sgy1[KCHUNK], sga[KCHUNK];
    __shared__ float sgcx[KCHUNK], sgcy[KCHUNK], sgw[KCHUNK], sgh[KCHUNK];
    __shared__ int   scls[KCHUNK];
    __shared__ int   sn;

    if (threadIdx.x == 0) sn = g_nvalid[b];
    __syncthreads();
    int n = sn;
    int kc1 = min(n, kc0 + KCHUNK);
    if (kc0 >= kc1) return;   // block-uniform

    for (int k = kc0 + threadIdx.x; k < kc1; k += blockDim.x) {
        int kk = k - kc0;
        int gi = g_vlist[b * GG + k];
        const float* gb = gboxes + ((size_t)(b * GG + gi)) * 4;
        float cx = gb[0], cy = gb[1], w = gb[2], h = gb[3];
        float x0 = cx - w * 0.5f, y0 = cy - h * 0.5f;
        float x1 = cx + w * 0.5f, y1 = cy + h * 0.5f;
        sgx0[kk] = x0; sgy0[kk] = y0; sgx1[kk] = x1; sgy1[kk] = y1;
        sga[kk] = fmaxf(x1 - x0, 0.f) * fmaxf(y1 - y0, 0.f);
        sgcx[kk] = cx; sgcy[kk] = cy; sgw[kk] = w; sgh[kk] = h;
        int c = gtc[b * GG + gi];
        scls[kk] = (c < 0) ? 0 : (c > NC - 1 ? NC - 1 : c);
    }
    __syncthreads();

    // softmax over NC1 logits
    const float* lg = logits + ((size_t)(b * QQ + qc)) * NC1;
    float e[NC1];
    float mx = lg[0];
#pragma unroll
    for (int c = 1; c < NC1; c++) mx = fmaxf(mx, lg[c]);
    float s = 0.f;
#pragma unroll
    for (int c = 0; c < NC1; c++) { e[c] = expf(lg[c] - mx); s += e[c]; }
    float inv_s = 1.0f / s;
    if (blockIdx.z == 0 && valid) g_logZ[b * QQ + q] = mx + logf(s);

    const float* pb = pboxes + ((size_t)(b * QQ + qc)) * 4;
    float pcx = pb[0], pcy = pb[1], pw = pb[2], ph = pb[3];
    float px0 = pcx - pw * 0.5f, py0 = pcy - ph * 0.5f;
    float px1 = pcx + pw * 0.5f, py1 = pcy + ph * 0.5f;
    float pa = fmaxf(px1 - px0, 0.f) * fmaxf(py1 - py0, 0.f);

    float* outc = g_costT + (size_t)b * GG * QQ + q;
    for (int k = kc0; k < kc1; k++) {
        int kk = k - kc0;
        float clsc = -(e[scls[kk]] * inv_s);
        float l1 = fabsf(pcx - sgcx[kk]) + fabsf(pcy - sgcy[kk]) +
                   fabsf(pw - sgw[kk]) + fabsf(ph - sgh[kk]);
        float gx0 = sgx0[kk], gy0 = sgy0[kk], gx1 = sgx1[kk], gy1 = sgy1[kk];
        float ltx = fmaxf(px0, gx0), lty = fmaxf(py0, gy0);
        float rbx = fminf(px1, gx1), rby = fminf(py1, gy1);
        float iw = fmaxf(rbx - ltx, 0.f), ih = fmaxf(rby - lty, 0.f);
        float inter = iw * ih;
        float uni = pa + sga[kk] - inter;
        float iou = inter / fmaxf(uni, 1e-6f);
        float ex0 = fminf(px0, gx0), ey0 = fminf(py0, gy0);
        float ex1 = fmaxf(px1, gx1), ey1 = fmaxf(py1, gy1);
        float ew = fmaxf(ex1 - ex0, 0.f), eh = fmaxf(ey1 - ey0, 0.f);
        float enc = ew * eh;
        float giou = iou - (enc - uni) / fmaxf(enc, 1e-6f);
        float cval = 2.0f * clsc + 5.0f * l1 - 2.0f * giou;
        if (valid) outc[(size_t)k * QQ] = cval;

        // fused row (min, argmin): 2 hardware reduces + 1 packed atomic/warp
        unsigned int key = valid ? fkey(cval) : 0xFFFFFFFFu;
        unsigned int mkey = __reduce_min_sync(0xffffffffu, key);
        unsigned int qsel = (key == mkey) ? (unsigned int)q : 0xFFFFFFFFu;
        unsigned int qmin = __reduce_min_sync(0xffffffffu, qsel);
        if (lane == 0 && mkey != 0xFFFFFFFFu)
            atomicMin(&g_rowpack[b * GG + k],
                      ((unsigned long long)mkey << 32) | qmin);
    }
}

// Warm-started Jonker-Volgenant, 2 warps per batch, float32 duals (v=0 start —
// the fp32-safe variant verified exact R4-R15). 0-based columns, root = -1.
// Cross-warp argmin: per-warp redux then packed-key min in smem (R12 config).
__global__ void __launch_bounds__(64) jv_kernel() {
    const int b = blockIdx.x;
    const int tid = threadIdx.x;
    const int wid = tid >> 5;
    const int lane = tid & 31;
    const int n = g_nvalid[b];
    const float FNAN = __int_as_float(0x7fc00000);

    __shared__ __align__(16) float sv[QQ + 4];     // v duals
    __shared__ __align__(16) float sminv[QQ + 4];  // path minima (NaN = used)
    __shared__ float su[GG];                       // u duals
    __shared__ int   sway[QQ + 4];
    __shared__ int   sp[QQ + 4];                   // assigned row per col, -1 free
    __shared__ int   susedList[GG + 2];
    __shared__ float sDused[GG + 2];
    __shared__ int   sfree[GG + 1];
    __shared__ unsigned long long srowpk[GG];
    __shared__ unsigned long long swcomb[2];
    __shared__ int   snfree;

    for (int q = tid; q < QQ + 4; q += 64) { sv[q] = 0.0f; sp[q] = -1; }
    for (int i = tid; i < n; i += 64) srowpk[i] = g_rowpack[b * GG + i];
    __syncthreads();

    // greedy assignment from row minima (decisions serial, data from LDS)
    if (tid == 0) {
        int nf = 0;
        for (int i = 0; i < n; i++) {
            unsigned long long pk = srowpk[i];
            su[i] = fkey_inv((unsigned int)(pk >> 32));
            int jm = (int)(pk & 0xFFFFFFFFull);
            if (sp[jm] < 0) sp[jm] = i;
            else sfree[nf++] = i;
        }
        snfree = nf;
    }
    __syncthreads();
    const int nfree = snfree;

    const float* Cbase = g_costT + (size_t)b * GG * QQ;

    for (int fi = 0; fi < nfree; fi++) {
        const int f = sfree[fi];
        // reset minv (vectorized, owner-exclusive)
#pragma unroll
        for (int s = 0; s < 4; s++) {
            int f4 = tid + (s << 6);
            if (f4 < NF4)
                *(float4*)&sminv[f4 << 2] = make_float4(1e30f, 1e30f, 1e30f, 1e30f);
        }
        __syncthreads();

        int i0 = f;
        int j0 = -1;       // root
        float D = 0.0f;
        int cnt = 0;

        while (true) {
            const float ueff = su[i0] - D;
            if (tid == 0) { susedList[cnt] = j0; sDused[cnt] = D; }
            if (j0 >= 0 && (((j0 >> 2) & 63) == tid)) sminv[j0] = FNAN; // owner marks used
            cnt++;

            const float4* __restrict__ Crow4 =
                (const float4*)(Cbase + (size_t)i0 * QQ);

            // batched vector loads: full MLP, one L2 round trip
            float4 c4[4];
#pragma unroll
            for (int s = 0; s < 4; s++) {
                int f4 = tid + (s << 6);
                c4[s] = (f4 < NF4) ? __ldg(&Crow4[f4])
                                   : make_float4(1e30f, 1e30f, 1e30f, 1e30f);
            }

            float lmin = 1e30f;
            int lq = QQ;
#pragma unroll
            for (int s = 0; s < 4; s++) {
                int f4 = tid + (s << 6);
                if (f4 < NF4) {
                    int q0 = f4 << 2;
                    float4 v4 = *(const float4*)&sv[q0];
                    float4 m4 = *(const float4*)&sminv[q0];
                    float cur;
                    cur = c4[s].x - ueff - v4.x;
                    if (cur < m4.x) { m4.x = cur; sway[q0] = j0; }       // false if NaN
                    cur = c4[s].y - ueff - v4.y;
                    if (cur < m4.y) { m4.y = cur; sway[q0 + 1] = j0; }
                    cur = c4[s].z - ueff - v4.z;
                    if (cur < m4.z) { m4.z = cur; sway[q0 + 2] = j0; }
                    cur = c4[s].w - ueff - v4.w;
                    if (cur < m4.w) { m4.w = cur; sway[q0 + 3] = j0; }
                    *(float4*)&sminv[q0] = m4;
                    if (m4.x < lmin) { lmin = m4.x; lq = q0; }           // NaN excluded
                    if (m4.y < lmin) { lmin = m4.y; lq = q0 + 1; }
                    if (m4.z < lmin) { lmin = m4.z; lq = q0 + 2; }
                    if (m4.w < lmin) { lmin = m4.w; lq = q0 + 3; }
                }
            }
            // per-warp argmin via hardware reduces, then cross-warp packed min
            unsigned int key = fkey(lmin);
            unsigned int mkey = __reduce_min_sync(0xffffffffu, key);
            unsigned int qsel = (key == mkey) ? (unsigned int)lq : 0xffffffffu;
            unsigned int qmin = __reduce_min_sync(0xffffffffu, qsel);
            if (lane == 0)
                swcomb[wid] = ((unsigned long long)mkey << 32) | qmin;
            __syncthreads();
            unsigned long long comb = min(swcomb[0], swcomb[1]);
            __syncthreads();   // protect swcomb reuse next phase
            D = fkey_inv((unsigned int)(comb >> 32));  // bit-identical to winner
            j0 = (int)(comb & 0xFFFFFFFFull);
            int pj = sp[j0];
            if (pj < 0) break;
            i0 = pj;
        }

        // commit duals over used columns (distinct rows & cols -> race-free)
        for (int t = tid; t < cnt; t += 64) {
            int j = susedList[t];
            float dd = D - sDused[t];
            if (j < 0) su[f] += dd;
            else { su[sp[j]] += dd; sv[j] -= dd; }
        }
        __syncthreads();
        if (tid == 0) {
            int jj = j0;
            while (jj >= 0) {
                int jn = sway[jj];
                sp[jj] = (jn < 0) ? f : sp[jn];
                jj = jn;
            }
        }
        __syncthreads();
    }

    for (int q = tid; q < QQ; q += 64) {
        int r = sp[q];
        g_match[b * QQ + q] = (r >= 0) ? g_vlist[b * GG + r] : -1;
    }
    if (tid == 0) atomicAdd(&g_nmatched, n);
}

// 225 blocks x 256 threads, one item per thread (the R12 shape that measured
// fastest) with last-block finalize.
__global__ void __launch_bounds__(256) loss_kernel(
        const float* __restrict__ logits,
        const float* __restrict__ pboxes,
        const int*   __restrict__ gtc,
        const float* __restrict__ gboxes,
        float* __restrict__ out) {
    int idx = blockIdx.x * blockDim.x + threadIdx.x;
    double nllw = 0.0, wsum = 0.0, l1acc = 0.0, glacc = 0.0;

    if (idx < BB * QQ) {
        int b = idx / QQ;
        int mg = g_match[idx];
        int t = (mg >= 0) ? __ldg(&gtc[b * GG + mg]) : NC;
        float logp = __ldg(&logits[(size_t)idx * NC1 + t]) - g_logZ[idx];
        float wt = (t == NC) ? 0.1f : 1.0f;
        nllw = (double)(wt * (-logp));
        wsum = (double)wt;

        if (mg >= 0) {
            const float* pb = pboxes + (size_t)idx * 4;
            const float* gb = gboxes + ((size_t)(b * GG + mg)) * 4;
            float pcx = pb[0], pcy = pb[1], pw = pb[2], ph = pb[3];
            float gcx = gb[0], gcy = gb[1], gw = gb[2], gh = gb[3];
            l1acc = (double)(fabsf(pcx - gcx) + fabsf(pcy - gcy) +
                             fabsf(pw - gw) + fabsf(ph - gh));
            float px0 = pcx - pw * 0.5f, py0 = pcy - ph * 0.5f;
            float px1 = pcx + pw * 0.5f, py1 = pcy + ph * 0.5f;
            float gx0 = gcx - gw * 0.5f, gy0 = gcy - gh * 0.5f;
            float gx1 = gcx + gw * 0.5f, gy1 = gcy + gh * 0.5f;
            float pa = fmaxf(px1 - px0, 0.f) * fmaxf(py1 - py0, 0.f);
            float ga = fmaxf(gx1 - gx0, 0.f) * fmaxf(gy1 - gy0, 0.f);
            float ltx = fmaxf(px0, gx0), lty = fmaxf(py0, gy0);
            float rbx = fminf(px1, gx1), rby = fminf(py1, gy1);
            float iw = fmaxf(rbx - ltx, 0.f), ih = fmaxf(rby - lty, 0.f);
            float inter = iw * ih;
            float uni = pa + ga - inter;
            float iou = inter / fmaxf(uni, 1e-6f);
            float ex0 = fminf(px0, gx0), ey0 = fminf(py0, gy0);
            float ex1 = fmaxf(px1, gx1), ey1 = fmaxf(py1, gy1);
            float ew = fmaxf(ex1 - ex0, 0.f), eh = fmaxf(ey1 - ey0, 0.f);
            float enc = ew * eh;
            float giou = iou - (enc - uni) / fmaxf(enc, 1e-6f);
            glacc = (double)(1.0f - giou);
        }
    }

    __shared__ double s1[256], s2[256], s3[256], s4[256];
    int tid = threadIdx.x;
    s1[tid] = nllw; s2[tid] = wsum; s3[tid] = l1acc; s4[tid] = glacc;
    __syncthreads();
#pragma unroll
    for (int s = 128; s > 0; s >>= 1) {
        if (tid < s) {
            s1[tid] += s1[tid + s];
            s2[tid] += s2[tid + s];
            s3[tid] += s3[tid + s];
            s4[tid] += s4[tid + s];
        }
        __syncthreads();
    }
    if (tid == 0) {
        atomicAdd(&g_cls_num, s1[0]);
        atomicAdd(&g_cls_den, s2[0]);
        atomicAdd(&g_l1, s3[0]);
        atomicAdd(&g_gl, s4[0]);
        __threadfence();
        int done = atomicAdd(&g_loss_done, 1);
        if (done == gridDim.x - 1) {   // last block finalizes
            int nm = g_nmatched;
            if (nm < 1) nm = 1;
            double nmd = (double)nm;
            double cls = g_cls_num / g_cls_den;
            out[0] = (float)(2.0 * cls + 5.0 * g_l1 / nmd + 2.0 * g_gl / nmd);
        }
    }
}

extern "C" void kernel_launch(void* const* d_in, const int* in_sizes, int n_in,
                              void* d_out, int out_size) {
    const float* pred_logits = (const float*)d_in[0];
    const float* pred_boxes  = (const float*)d_in[1];
    const int*   gt_classes  = (const int*)d_in[2];
    const float* gt_boxes    = (const float*)d_in[3];
    float* out = (float*)d_out;

    prep_kernel<<<BB, 128>>>(gt_classes);

    dim3 cgrid((QQ + 127) / 128, BB, (GG + KCHUNK - 1) / KCHUNK);
    cost_kernel<<<cgrid, 128>>>(pred_logits, pred_boxes, gt_classes, gt_boxes);

    jv_kernel<<<BB, 64>>>();

    int total = BB * QQ;
    loss_kernel<<<(total + 255) / 256, 256>>>(pred_logits, pred_boxes,
                                              gt_classes, gt_boxes, out);
}